// round 14
// baseline (speedup 1.0000x reference)
#include <cuda_runtime.h>
#include <cuda_bf16.h>
#include <math.h>
#include <stdint.h>

// Problem constants
#define N1 8
#define N2 8
#define P  1024
#define D  768
#define PH 32
#define PW 32
#define OH 512
#define OW 512

// GEMM tiling — INT8 IMMA path (mma.sync m16n8k32.s8), q-split units.
#define BM 128
#define BN 128
#define BK 64                     // 64 int8 = 64B per tile row
#define STAGES 4                  // 4-deep ring: 2 groups of latency slack
#define KSTEPS (D / BK)           // 12
#define QSTEPS_U 4                // q-tiles per unit (half of 8)
#define NSTEP  (KSTEPS * QSTEPS_U)  // 48
#define TILE_BYTES  8192          // 128 rows * 64 B
#define STAGE_BYTES (2 * TILE_BYTES)
#define SMEM_TILES  (STAGES * STAGE_BYTES)   // 65536
#define SMEM_SBV    SMEM_TILES               // 128 floats of B scales
#define SMEM_DYN    (SMEM_TILES + 512)

// Scratch (no cudaMalloc allowed)
__device__ int8_t g_Fq[N1 * P * D];   // normalized feats, int8 (per-row scaled)
__device__ int8_t g_Gq[N2 * P * D];   // normalized nfeats, int8
__device__ float  g_sF[N1 * P];       // per-row scales for F
__device__ float  g_sG[N2 * P];       // per-row scales for G
__device__ float  g_spatch[N1 * N2 * P];  // biased max cos: cmax*sF + 2 (atomic)

// ---------------------------------------------------------------------------
// Helpers
// ---------------------------------------------------------------------------
__device__ __forceinline__ uint32_t cvta_s(const void* p) {
    return (uint32_t)__cvta_generic_to_shared(p);
}

#define CPA16(dst, src) \
    asm volatile("cp.async.cg.shared.global [%0], [%1], 16;\n" :: "r"(dst), "l"(src))
#define CPA_COMMIT()  asm volatile("cp.async.commit_group;\n" ::: "memory")
#define CPA_WAIT2()   asm volatile("cp.async.wait_group 2;\n" ::: "memory")

__device__ __forceinline__ void ldsm4(uint32_t& r0, uint32_t& r1, uint32_t& r2,
                                      uint32_t& r3, uint32_t a) {
    asm volatile("ldmatrix.sync.aligned.m8n8.x4.shared.b16 {%0,%1,%2,%3}, [%4];\n"
                 : "=r"(r0), "=r"(r1), "=r"(r2), "=r"(r3) : "r"(a));
}

__device__ __forceinline__ void mma16832s8(int* c, const uint32_t* a,
                                           const uint32_t* b) {
    asm volatile(
        "mma.sync.aligned.m16n8k32.row.col.s32.s8.s8.s32 "
        "{%0,%1,%2,%3}, {%4,%5,%6,%7}, {%8,%9}, {%0,%1,%2,%3};\n"
        : "+r"(c[0]), "+r"(c[1]), "+r"(c[2]), "+r"(c[3])
        : "r"(a[0]), "r"(a[1]), "r"(a[2]), "r"(a[3]), "r"(b[0]), "r"(b[1]));
}

// Tile row = 64 int8 = 64B = 4 chunks of 16B. XOR swizzle: conflict-free
// ldmatrix (8 rows at fixed logical chunk hit 8 distinct 16B slots mod 128B).
__device__ __forceinline__ uint32_t swaddr(int row, int ch) {
    return (uint32_t)((row << 6) | (((ch ^ ((row >> 1) & 3)) & 3) << 4));
}

// key -> dist: dist = 0.5*sqrt(max(2 - 2*(key-2), 0))
__device__ __forceinline__ float key2dist(float key) {
    float c = key - 2.0f;
    return 0.5f * sqrtf(fmaxf(2.0f - 2.0f * c, 0.0f));
}

// ---------------------------------------------------------------------------
// Kernel 1: row-normalize -> per-row-scaled int8; also zero-init g_spatch.
// Single fused reduction round: q = round(x*127/amax(x)) needs no rnorm;
// the stored dequant scale is amax(x)*rnorm/127. grid = 16384 rows, block 192
// ---------------------------------------------------------------------------
__global__ void norm_k(const float* __restrict__ feats,
                       const float* __restrict__ nfeats) {
    int row = blockIdx.x;

    // init g_spatch (keys are >= 0.95, so 0.0f is the identity for float-max)
    if (row < N1 * N2) {
        for (int i = threadIdx.x; i < P; i += blockDim.x)
            g_spatch[(size_t)row * P + i] = 0.0f;
    }

    const float* src;
    int8_t* dst;
    float* sdst;
    int srow;
    if (row < N1 * P) {
        src = feats + (size_t)row * D;
        dst = g_Fq + (size_t)row * D;
        sdst = g_sF; srow = row;
    } else {
        int r = row - N1 * P;
        src = nfeats + (size_t)r * D;
        dst = g_Gq + (size_t)r * D;
        sdst = g_sG; srow = r;
    }
    int t = threadIdx.x;  // 0..191
    float4 x = *(const float4*)(src + t * 4);
    float s = x.x * x.x + x.y * x.y + x.z * x.z + x.w * x.w;
    float am = fmaxf(fmaxf(fabsf(x.x), fabsf(x.y)),
                     fmaxf(fabsf(x.z), fabsf(x.w)));
    #pragma unroll
    for (int off = 16; off; off >>= 1) {
        s  += __shfl_xor_sync(0xffffffffu, s, off);
        am  = fmaxf(am, __shfl_xor_sync(0xffffffffu, am, off));
    }
    __shared__ float ws[6], wm[6];
    __shared__ float scale_s, sc_out;
    if ((t & 31) == 0) { ws[t >> 5] = s; wm[t >> 5] = am; }
    __syncthreads();
    if (t == 0) {
        float tot = 0.f, mx = 0.f;
        #pragma unroll
        for (int i = 0; i < 6; i++) { tot += ws[i]; mx = fmaxf(mx, wm[i]); }
        float rnorm = rsqrtf(tot);
        scale_s = 127.0f / mx;                  // raw-x quantizer
        sc_out  = mx * rnorm * (1.0f / 127.0f); // dequant scale (unit-norm space)
    }
    __syncthreads();
    if (t == 0) sdst[srow] = sc_out;
    float scale = scale_s;
    int q0 = __float2int_rn(x.x * scale);
    int q1 = __float2int_rn(x.y * scale);
    int q2 = __float2int_rn(x.z * scale);
    int q3 = __float2int_rn(x.w * scale);
    uint32_t pk = (uint32_t)(q0 & 0xff) | ((uint32_t)(q1 & 0xff) << 8) |
                  ((uint32_t)(q2 & 0xff) << 16) | ((uint32_t)(q3 & 0xff) << 24);
    *(uint32_t*)(dst + t * 4) = pk;
}

// ---------------------------------------------------------------------------
// Kernel 2: int8 tensor-core batched GEMM + running (scaled) max over q.
// grid = (8 p-blocks, 128 = pair*2 + qhalf): 1024 units of 48 steps.
// 4-stage cp.async ring; byte-identical to R13 (at IMMA issue ceiling).
// ---------------------------------------------------------------------------
__global__ __launch_bounds__(256, 2)
void gemm_max_k() {
    extern __shared__ __align__(1024) unsigned char smem[];
    const uint32_t sbase = cvta_s(smem);
    float* sbv = (float*)(smem + SMEM_SBV);  // B scales for current q-pass

    const int pair = blockIdx.y >> 1;
    const int qh   = blockIdx.y & 1;         // q-half: 0 -> q 0..511, 1 -> 512..1023
    const int qbase = qh * (QSTEPS_U * BN);  // 0 or 512
    const int8_t* __restrict__ Fb = g_Fq + (size_t)(pair >> 3) * P * D;
    const int8_t* __restrict__ Gb = g_Gq + (size_t)(pair & 7) * P * D;
    const float* __restrict__ sFp = g_sF + (size_t)(pair >> 3) * P;
    const float* __restrict__ sGp = g_sG + (size_t)(pair & 7) * P;
    const int p0 = blockIdx.x * BM;

    const int tid  = threadIdx.x;
    const int lane = tid & 31;
    const int wid  = tid >> 5;
    const int wrow = (wid >> 2) * 64;  // warp m offset (0 / 64)
    const int wcol = (wid & 3) * 32;   // warp n offset (0..96)

    // loader mapping: thread -> (row = tid>>2 [+64], chunk = tid&3)
    const int lrow   = tid >> 2;  // 0..63
    const int lchunk = tid & 3;
    const uint32_t dA0 = swaddr(lrow, lchunk);
    const uint32_t dA1 = swaddr(lrow + 64, lchunk);

    int acc[4][4][4];
    float cmax[4][2];
    #pragma unroll
    for (int i = 0; i < 4; i++) { cmax[i][0] = -1e30f; cmax[i][1] = -1e30f; }
    #pragma unroll
    for (int i = 0; i < 4; i++)
        #pragma unroll
        for (int j = 0; j < 4; j++)
            #pragma unroll
            for (int e = 0; e < 4; e++) acc[i][j][e] = 0;

    // -------- cp.async tile loader for flattened step s --------
    auto load_step = [&](int s) {
        int q0 = qbase + (s / KSTEPS) * BN;
        int k0 = (s % KSTEPS) * BK;
        uint32_t Ab = sbase + (s % STAGES) * STAGE_BYTES;
        uint32_t Bb = Ab + TILE_BYTES;
        int ke = k0 + lchunk * 16;  // int8 elements
        CPA16(Ab + dA0, Fb + ((size_t)(p0 + lrow) * D + ke));
        CPA16(Ab + dA1, Fb + ((size_t)(p0 + lrow + 64) * D + ke));
        CPA16(Bb + dA0, Gb + ((size_t)(q0 + lrow) * D + ke));
        CPA16(Bb + dA1, Gb + ((size_t)(q0 + lrow + 64) * D + ke));
    };

    // prologue: fill STAGES-1 = 3 stages
    #pragma unroll
    for (int s = 0; s < STAGES - 1; s++) {
        load_step(s);
        CPA_COMMIT();
    }

    // per-warp ldmatrix lane offsets
    const int mr = lane & 15;        // row-within-16 for ldsm
    const int cl = lane >> 4;        // 16B chunk select (0/1)
    const int qb = wcol + 2 * (lane & 3);  // this lane's base q col in tile

    int kc = 0;  // position within current q-pass
    for (int s = 0; s < NSTEP; s++) {
        CPA_WAIT2();   // step-s group done; groups s+1, s+2 may remain in flight
        __syncthreads();

        // q-pass start: stage B scales for the fold (ordered by later syncs)
        if (kc == 0 && tid < 128)
            sbv[tid] = sGp[qbase + (s / KSTEPS) * BN + tid];

        uint32_t Ab = sbase + (s % STAGES) * STAGE_BYTES;
        uint32_t Bb = Ab + TILE_BYTES;

        #pragma unroll
        for (int hk = 0; hk < 2; hk++) {  // two k32 groups in BK=64
            uint32_t a[4][4], b[4][2];
            #pragma unroll
            for (int i = 0; i < 4; i++)
                ldsm4(a[i][0], a[i][1], a[i][2], a[i][3],
                      Ab + swaddr(wrow + i * 16 + mr, hk * 2 + cl));
            #pragma unroll
            for (int j = 0; j < 2; j++) {
                uint32_t r0, r1, r2, r3;
                ldsm4(r0, r1, r2, r3,
                      Bb + swaddr(wcol + j * 16 + mr, hk * 2 + cl));
                b[2 * j][0] = r0;     b[2 * j][1] = r2;
                b[2 * j + 1][0] = r1; b[2 * j + 1][1] = r3;
            }
            #pragma unroll
            for (int i = 0; i < 4; i++)
                #pragma unroll
                for (int j = 0; j < 4; j++)
                    mma16832s8(acc[i][j], a[i], b[j]);
        }

        // issue next stage (stage (s+3)%4 was last read at step s-1)
        if (s + STAGES - 1 < NSTEP) load_step(s + STAGES - 1);
        CPA_COMMIT();

        if (++kc == KSTEPS) {  // end of a q-pass: scale by sb[q], fold max
            kc = 0;
            #pragma unroll
            for (int i = 0; i < 4; i++) {
                float m0 = cmax[i][0], m1 = cmax[i][1];
                #pragma unroll
                for (int j = 0; j < 4; j++) {
                    float s0 = sbv[qb + j * 8];
                    float s1 = sbv[qb + j * 8 + 1];
                    m0 = fmaxf(m0, fmaxf((float)acc[i][j][0] * s0,
                                         (float)acc[i][j][1] * s1));
                    m1 = fmaxf(m1, fmaxf((float)acc[i][j][2] * s0,
                                         (float)acc[i][j][3] * s1));
                    acc[i][j][0] = 0; acc[i][j][1] = 0;
                    acc[i][j][2] = 0; acc[i][j][3] = 0;
                }
                cmax[i][0] = m0; cmax[i][1] = m1;
            }
        }
    }

    // reduce max over quad lanes (columns live in lane&3; sb already applied)
    #pragma unroll
    for (int i = 0; i < 4; i++) {
        #pragma unroll
        for (int e = 0; e < 2; e++) {
            float v = cmax[i][e];
            v = fmaxf(v, __shfl_xor_sync(0xffffffffu, v, 1));
            v = fmaxf(v, __shfl_xor_sync(0xffffffffu, v, 2));
            cmax[i][e] = v;
        }
    }

    __syncthreads();  // tiles dead; reuse smem for cross-warp max
    float* red = (float*)smem;  // [4 warp_cols][128 rows]
    if ((lane & 3) == 0) {
        int base = (wid & 3) * 128 + wrow;
        int r = lane >> 2;  // 0..7
        #pragma unroll
        for (int i = 0; i < 4; i++) {
            red[base + i * 16 + r]     = cmax[i][0];
            red[base + i * 16 + r + 8] = cmax[i][1];
        }
    }
    __syncthreads();
    if (tid < 128) {
        float v = red[tid];
        v = fmaxf(v, red[128 + tid]);
        v = fmaxf(v, red[256 + tid]);
        v = fmaxf(v, red[384 + tid]);
        v = v * sFp[p0 + tid] + 2.0f;  // key in [0.95, 3.05] > 0: int-max valid
        atomicMax((int*)&g_spatch[(size_t)pair * P + p0 + tid],
                  __float_as_int(v));
    }
}

// ---------------------------------------------------------------------------
// Kernel 3 (fused post): blocks 0..7 -> scores[n]; blocks 8.. -> resize rows.
// Resize blocks recompute their two 32-entry sp rows from g_spatch keys
// (identical m-ascending arithmetic order as before -> bit-identical output).
// grid = 8 + 8*512 = 4104, block = 128.
// ---------------------------------------------------------------------------
__global__ void post_k(float* __restrict__ out) {
    const int t = threadIdx.x;

    if (blockIdx.x < N1) {  // ---- scores block ----
        const int n = blockIdx.x;
        float tmax[8];
        #pragma unroll
        for (int m = 0; m < 8; m++) tmax[m] = 0.f;
        #pragma unroll
        for (int i = 0; i < 8; i++) {
            int p = t + 128 * i;
            #pragma unroll
            for (int m = 0; m < 8; m++) {
                float d = key2dist(g_spatch[(size_t)(n * 8 + m) * P + p]);
                tmax[m] = fmaxf(tmax[m], d);
            }
        }
        __shared__ int smax[8];
        if (t < 8) smax[t] = 0;  // dist >= 0: int-compare == float-compare
        __syncthreads();
        #pragma unroll
        for (int m = 0; m < 8; m++) {
            float x = tmax[m];
            #pragma unroll
            for (int off = 16; off; off >>= 1)
                x = fmaxf(x, __shfl_xor_sync(0xffffffffu, x, off));
            if ((t & 31) == 0) atomicMax(&smax[m], __float_as_int(x));
        }
        __syncthreads();
        if (t == 0) {
            float s = 0.f;
            #pragma unroll
            for (int m = 0; m < 8; m++) s += __int_as_float(smax[m]);
            out[n] = s * 0.125f;
        }
        return;
    }

    // ---- resize block ----
    const int b = blockIdx.x - N1;
    const int n = b >> 9;                  // image
    const int r = b & (OH - 1);            // output row
    float* __restrict__ pix = out + N1;

    __shared__ float r0s[PW], r1s[PW];
    float sy = (r + 0.5f) * ((float)PH / OH) - 0.5f;
    {
        float y0f = floorf(sy);
        int y0 = min(max((int)y0f, 0), PH - 1);
        int y1 = min(max((int)y0f + 1, 0), PH - 1);
        if (t < 2 * PW) {  // recompute sp entry from keys (m-ascending order)
            int srow = (t < PW) ? y0 : y1;
            int col = (t < PW) ? t : (t - PW);
            int p = srow * PW + col;
            float s = 0.f;
            #pragma unroll
            for (int m = 0; m < 8; m++)
                s += key2dist(g_spatch[(size_t)(n * 8 + m) * P + p]);
            float sp = s * 0.125f;
            if (t < PW) r0s[col] = sp;
            else        r1s[col] = sp;
        }
    }
    __syncthreads();

    float wy = sy - floorf(sy);
    float4 o;
    float* op = &o.x;
    #pragma unroll
    for (int k = 0; k < 4; k++) {
        int c = 4 * t + k;
        float sx = (c + 0.5f) * ((float)PW / OW) - 0.5f;
        float x0f = floorf(sx);
        float wx = sx - x0f;
        int x0 = min(max((int)x0f, 0), PW - 1);
        int x1 = min(max((int)x0f + 1, 0), PW - 1);
        float top = r0s[x0] + (r0s[x1] - r0s[x0]) * wx;
        float bot = r1s[x0] + (r1s[x1] - r1s[x0]) * wx;
        op[k] = top + (bot - top) * wy;
    }
    *(float4*)(pix + ((size_t)n * OH + r) * OW + 4 * t) = o;
}

// ---------------------------------------------------------------------------
extern "C" void kernel_launch(void* const* d_in, const int* in_sizes, int n_in,
                              void* d_out, int out_size) {
    (void)in_sizes; (void)n_in; (void)out_size;
    const float* feats  = (const float*)d_in[0];
    const float* nfeats = (const float*)d_in[1];
    float* out = (float*)d_out;  // [0..7] = scores, [8..] = scores_pixel

    cudaFuncSetAttribute(gemm_max_k,
                         cudaFuncAttributeMaxDynamicSharedMemorySize, SMEM_DYN);

    norm_k<<<(N1 + N2) * P, 192>>>(feats, nfeats);
    dim3 ggrid(P / BM, N1 * N2 * 2);  // 1024 units: (pblock, pair*2 + qhalf)
    gemm_max_k<<<ggrid, 256, SMEM_DYN>>>();
    post_k<<<N1 + N1 * OH, 128>>>(out);
}

// round 15
// speedup vs baseline: 1.0923x; 1.0923x over previous
#include <cuda_runtime.h>
#include <cuda_bf16.h>
#include <math.h>
#include <stdint.h>

// Problem constants
#define N1 8
#define N2 8
#define P  1024
#define D  768
#define PH 32
#define PW 32
#define OH 512
#define OW 512

// GEMM tiling — INT8 IMMA path (mma.sync m16n8k32.s8), q-split units.
#define BM 128
#define BN 128
#define BK 64                     // 64 int8 = 64B per tile row
#define STAGES 4                  // 4-deep ring: 2 groups of latency slack
#define KSTEPS (D / BK)           // 12
#define QSTEPS_U 4                // q-tiles per unit (half of 8)
#define NSTEP  (KSTEPS * QSTEPS_U)  // 48
#define TILE_BYTES  8192          // 128 rows * 64 B
#define STAGE_BYTES (2 * TILE_BYTES)
#define SMEM_TILES  (STAGES * STAGE_BYTES)   // 65536
#define SMEM_SBV    SMEM_TILES               // 128 floats of B scales
#define SMEM_DYN    (SMEM_TILES + 512)

// Scratch (no cudaMalloc allowed)
__device__ int8_t g_Fq[N1 * P * D];   // normalized feats, int8 (per-row scaled)
__device__ int8_t g_Gq[N2 * P * D];   // normalized nfeats, int8
__device__ float  g_sF[N1 * P];       // per-row scales for F
__device__ float  g_sG[N2 * P];       // per-row scales for G
__device__ float  g_spatch[N1 * N2 * P];  // biased max cos: cmax*sF + 2 (atomic)
__device__ float  g_sp[N1 * P];       // mean over m

// ---------------------------------------------------------------------------
// Helpers
// ---------------------------------------------------------------------------
__device__ __forceinline__ uint32_t cvta_s(const void* p) {
    return (uint32_t)__cvta_generic_to_shared(p);
}

#define CPA16(dst, src) \
    asm volatile("cp.async.cg.shared.global [%0], [%1], 16;\n" :: "r"(dst), "l"(src))
#define CPA_COMMIT()  asm volatile("cp.async.commit_group;\n" ::: "memory")
#define CPA_WAIT2()   asm volatile("cp.async.wait_group 2;\n" ::: "memory")

__device__ __forceinline__ void ldsm4(uint32_t& r0, uint32_t& r1, uint32_t& r2,
                                      uint32_t& r3, uint32_t a) {
    asm volatile("ldmatrix.sync.aligned.m8n8.x4.shared.b16 {%0,%1,%2,%3}, [%4];\n"
                 : "=r"(r0), "=r"(r1), "=r"(r2), "=r"(r3) : "r"(a));
}

__device__ __forceinline__ void mma16832s8(int* c, const uint32_t* a,
                                           const uint32_t* b) {
    asm volatile(
        "mma.sync.aligned.m16n8k32.row.col.s32.s8.s8.s32 "
        "{%0,%1,%2,%3}, {%4,%5,%6,%7}, {%8,%9}, {%0,%1,%2,%3};\n"
        : "+r"(c[0]), "+r"(c[1]), "+r"(c[2]), "+r"(c[3])
        : "r"(a[0]), "r"(a[1]), "r"(a[2]), "r"(a[3]), "r"(b[0]), "r"(b[1]));
}

// Tile row = 64 int8 = 64B = 4 chunks of 16B. XOR swizzle: conflict-free
// ldmatrix (8 rows at fixed logical chunk hit 8 distinct 16B slots mod 128B).
__device__ __forceinline__ uint32_t swaddr(int row, int ch) {
    return (uint32_t)((row << 6) | (((ch ^ ((row >> 1) & 3)) & 3) << 4));
}

// ---------------------------------------------------------------------------
// Kernel 1: row-normalize -> per-row-scaled int8, warp-per-row (no block
// barriers; MLP=6 per lane hides DRAM latency). Also zero-init g_spatch.
// grid = 2048 blocks x 256 threads (8 warps = 8 rows per block).
// ---------------------------------------------------------------------------
__global__ void norm_k(const float* __restrict__ feats,
                       const float* __restrict__ nfeats) {
    const int t = threadIdx.x;

    // init g_spatch: first 256 blocks zero 256 entries each (65536 total).
    // Keys are >= 0.95, so 0.0f is the identity for float-max.
    if (blockIdx.x < 256)
        g_spatch[(size_t)blockIdx.x * 256 + t] = 0.0f;

    const int row = blockIdx.x * 8 + (t >> 5);  // 0..16383
    const int lane = t & 31;

    const float* src;
    int8_t* dst;
    float* sdst;
    int srow;
    if (row < N1 * P) {
        src = feats + (size_t)row * D;
        dst = g_Fq + (size_t)row * D;
        sdst = g_sF; srow = row;
    } else {
        int r = row - N1 * P;
        src = nfeats + (size_t)r * D;
        dst = g_Gq + (size_t)r * D;
        sdst = g_sG; srow = r;
    }

    // 6 float4 per lane: indices lane + 32*i (coalesced)
    float4 x[6];
    float s = 0.f, am = 0.f;
    #pragma unroll
    for (int i = 0; i < 6; i++) {
        x[i] = *(const float4*)(src + (lane + 32 * i) * 4);
        s += x[i].x * x[i].x + x[i].y * x[i].y +
             x[i].z * x[i].z + x[i].w * x[i].w;
        am = fmaxf(am, fmaxf(fmaxf(fabsf(x[i].x), fabsf(x[i].y)),
                             fmaxf(fabsf(x[i].z), fabsf(x[i].w))));
    }
    #pragma unroll
    for (int off = 16; off; off >>= 1) {
        s  += __shfl_xor_sync(0xffffffffu, s, off);
        am  = fmaxf(am, __shfl_xor_sync(0xffffffffu, am, off));
    }
    // all lanes now hold the full-row sum and amax
    float scale = 127.0f / am;                         // raw-x quantizer
    if (lane == 0)
        sdst[srow] = am * rsqrtf(s) * (1.0f / 127.0f); // dequant scale

    #pragma unroll
    for (int i = 0; i < 6; i++) {
        int q0 = __float2int_rn(x[i].x * scale);
        int q1 = __float2int_rn(x[i].y * scale);
        int q2 = __float2int_rn(x[i].z * scale);
        int q3 = __float2int_rn(x[i].w * scale);
        uint32_t pk = (uint32_t)(q0 & 0xff) | ((uint32_t)(q1 & 0xff) << 8) |
                      ((uint32_t)(q2 & 0xff) << 16) | ((uint32_t)(q3 & 0xff) << 24);
        *(uint32_t*)(dst + (lane + 32 * i) * 4) = pk;
    }
}

// ---------------------------------------------------------------------------
// Kernel 2: int8 tensor-core batched GEMM + running (scaled) max over q.
// grid = (8 p-blocks, 128 = pair*2 + qhalf): 1024 units of 48 steps.
// 4-stage cp.async ring; byte-identical to R13 (at IMMA issue ceiling).
// ---------------------------------------------------------------------------
__global__ __launch_bounds__(256, 2)
void gemm_max_k() {
    extern __shared__ __align__(1024) unsigned char smem[];
    const uint32_t sbase = cvta_s(smem);
    float* sbv = (float*)(smem + SMEM_SBV);  // B scales for current q-pass

    const int pair = blockIdx.y >> 1;
    const int qh   = blockIdx.y & 1;         // q-half: 0 -> q 0..511, 1 -> 512..1023
    const int qbase = qh * (QSTEPS_U * BN);  // 0 or 512
    const int8_t* __restrict__ Fb = g_Fq + (size_t)(pair >> 3) * P * D;
    const int8_t* __restrict__ Gb = g_Gq + (size_t)(pair & 7) * P * D;
    const float* __restrict__ sFp = g_sF + (size_t)(pair >> 3) * P;
    const float* __restrict__ sGp = g_sG + (size_t)(pair & 7) * P;
    const int p0 = blockIdx.x * BM;

    const int tid  = threadIdx.x;
    const int lane = tid & 31;
    const int wid  = tid >> 5;
    const int wrow = (wid >> 2) * 64;  // warp m offset (0 / 64)
    const int wcol = (wid & 3) * 32;   // warp n offset (0..96)

    // loader mapping: thread -> (row = tid>>2 [+64], chunk = tid&3)
    const int lrow   = tid >> 2;  // 0..63
    const int lchunk = tid & 3;
    const uint32_t dA0 = swaddr(lrow, lchunk);
    const uint32_t dA1 = swaddr(lrow + 64, lchunk);

    int acc[4][4][4];
    float cmax[4][2];
    #pragma unroll
    for (int i = 0; i < 4; i++) { cmax[i][0] = -1e30f; cmax[i][1] = -1e30f; }
    #pragma unroll
    for (int i = 0; i < 4; i++)
        #pragma unroll
        for (int j = 0; j < 4; j++)
            #pragma unroll
            for (int e = 0; e < 4; e++) acc[i][j][e] = 0;

    // -------- cp.async tile loader for flattened step s --------
    auto load_step = [&](int s) {
        int q0 = qbase + (s / KSTEPS) * BN;
        int k0 = (s % KSTEPS) * BK;
        uint32_t Ab = sbase + (s % STAGES) * STAGE_BYTES;
        uint32_t Bb = Ab + TILE_BYTES;
        int ke = k0 + lchunk * 16;  // int8 elements
        CPA16(Ab + dA0, Fb + ((size_t)(p0 + lrow) * D + ke));
        CPA16(Ab + dA1, Fb + ((size_t)(p0 + lrow + 64) * D + ke));
        CPA16(Bb + dA0, Gb + ((size_t)(q0 + lrow) * D + ke));
        CPA16(Bb + dA1, Gb + ((size_t)(q0 + lrow + 64) * D + ke));
    };

    // prologue: fill STAGES-1 = 3 stages
    #pragma unroll
    for (int s = 0; s < STAGES - 1; s++) {
        load_step(s);
        CPA_COMMIT();
    }

    // per-warp ldmatrix lane offsets
    const int mr = lane & 15;        // row-within-16 for ldsm
    const int cl = lane >> 4;        // 16B chunk select (0/1)
    const int qb = wcol + 2 * (lane & 3);  // this lane's base q col in tile

    int kc = 0;  // position within current q-pass
    for (int s = 0; s < NSTEP; s++) {
        CPA_WAIT2();   // step-s group done; groups s+1, s+2 may remain in flight
        __syncthreads();

        // q-pass start: stage B scales for the fold (ordered by later syncs)
        if (kc == 0 && tid < 128)
            sbv[tid] = sGp[qbase + (s / KSTEPS) * BN + tid];

        uint32_t Ab = sbase + (s % STAGES) * STAGE_BYTES;
        uint32_t Bb = Ab + TILE_BYTES;

        #pragma unroll
        for (int hk = 0; hk < 2; hk++) {  // two k32 groups in BK=64
            uint32_t a[4][4], b[4][2];
            #pragma unroll
            for (int i = 0; i < 4; i++)
                ldsm4(a[i][0], a[i][1], a[i][2], a[i][3],
                      Ab + swaddr(wrow + i * 16 + mr, hk * 2 + cl));
            #pragma unroll
            for (int j = 0; j < 2; j++) {
                uint32_t r0, r1, r2, r3;
                ldsm4(r0, r1, r2, r3,
                      Bb + swaddr(wcol + j * 16 + mr, hk * 2 + cl));
                b[2 * j][0] = r0;     b[2 * j][1] = r2;
                b[2 * j + 1][0] = r1; b[2 * j + 1][1] = r3;
            }
            #pragma unroll
            for (int i = 0; i < 4; i++)
                #pragma unroll
                for (int j = 0; j < 4; j++)
                    mma16832s8(acc[i][j], a[i], b[j]);
        }

        // issue next stage (stage (s+3)%4 was last read at step s-1)
        if (s + STAGES - 1 < NSTEP) load_step(s + STAGES - 1);
        CPA_COMMIT();

        if (++kc == KSTEPS) {  // end of a q-pass: scale by sb[q], fold max
            kc = 0;
            #pragma unroll
            for (int i = 0; i < 4; i++) {
                float m0 = cmax[i][0], m1 = cmax[i][1];
                #pragma unroll
                for (int j = 0; j < 4; j++) {
                    float s0 = sbv[qb + j * 8];
                    float s1 = sbv[qb + j * 8 + 1];
                    m0 = fmaxf(m0, fmaxf((float)acc[i][j][0] * s0,
                                         (float)acc[i][j][1] * s1));
                    m1 = fmaxf(m1, fmaxf((float)acc[i][j][2] * s0,
                                         (float)acc[i][j][3] * s1));
                    acc[i][j][0] = 0; acc[i][j][1] = 0;
                    acc[i][j][2] = 0; acc[i][j][3] = 0;
                }
                cmax[i][0] = m0; cmax[i][1] = m1;
            }
        }
    }

    // reduce max over quad lanes (columns live in lane&3; sb already applied)
    #pragma unroll
    for (int i = 0; i < 4; i++) {
        #pragma unroll
        for (int e = 0; e < 2; e++) {
            float v = cmax[i][e];
            v = fmaxf(v, __shfl_xor_sync(0xffffffffu, v, 1));
            v = fmaxf(v, __shfl_xor_sync(0xffffffffu, v, 2));
            cmax[i][e] = v;
        }
    }

    __syncthreads();  // tiles dead; reuse smem for cross-warp max
    float* red = (float*)smem;  // [4 warp_cols][128 rows]
    if ((lane & 3) == 0) {
        int base = (wid & 3) * 128 + wrow;
        int r = lane >> 2;  // 0..7
        #pragma unroll
        for (int i = 0; i < 4; i++) {
            red[base + i * 16 + r]     = cmax[i][0];
            red[base + i * 16 + r + 8] = cmax[i][1];
        }
    }
    __syncthreads();
    if (tid < 128) {
        float v = red[tid];
        v = fmaxf(v, red[128 + tid]);
        v = fmaxf(v, red[256 + tid]);
        v = fmaxf(v, red[384 + tid]);
        v = v * sFp[p0 + tid] + 2.0f;  // key in [0.95, 3.05] > 0: int-max valid
        atomicMax((int*)&g_spatch[(size_t)pair * P + p0 + tid],
                  __float_as_int(v));
    }
}

// ---------------------------------------------------------------------------
// Kernel 3: decode keys -> dist, then scores[n] = mean_m max_p,
// sp[n][p] = mean_m. dist = 0.5*sqrt(max(2 - 2*(key-2), 0)).
// ---------------------------------------------------------------------------
__global__ void reduce_k(float* __restrict__ scores) {
    const int n = blockIdx.x;
    const int p = threadIdx.x;
    float v[8];
    float s = 0.f;
    #pragma unroll
    for (int m = 0; m < 8; m++) {
        float key = g_spatch[(size_t)(n * 8 + m) * P + p];
        float c = key - 2.0f;
        v[m] = 0.5f * sqrtf(fmaxf(2.0f - 2.0f * c, 0.0f));
        s += v[m];
    }
    g_sp[n * P + p] = s * 0.125f;

    __shared__ int smax[8];
    if (p < 8) smax[p] = 0;  // dist >= 0 so int-compare == float-compare
    __syncthreads();
    #pragma unroll
    for (int m = 0; m < 8; m++) {
        float x = v[m];
        #pragma unroll
        for (int off = 16; off; off >>= 1)
            x = fmaxf(x, __shfl_xor_sync(0xffffffffu, x, off));
        if ((p & 31) == 0) atomicMax(&smax[m], __float_as_int(x));
    }
    __syncthreads();
    if (p == 0) {
        float t = 0.f;
        #pragma unroll
        for (int m = 0; m < 8; m++) t += __int_as_float(smax[m]);
        scores[n] = t * 0.125f;
    }
}

// ---------------------------------------------------------------------------
// Kernel 4: bilinear resize (8,32,32) -> (8,512,512).
// One block per output row; source rows staged in smem; each thread writes
// one float4 (4 pixels). grid = 8*512, block = 128.
// ---------------------------------------------------------------------------
__global__ void resize_k(float* __restrict__ out) {
    const int n = blockIdx.x >> 9;         // image
    const int r = blockIdx.x & (OH - 1);   // output row
    const int t = threadIdx.x;             // 0..127, pixels 4t..4t+3

    __shared__ float r0s[PW], r1s[PW];
    {
        float sy = (r + 0.5f) * ((float)PH / OH) - 0.5f;
        float y0f = floorf(sy);
        int y0 = min(max((int)y0f, 0), PH - 1);
        int y1 = min(max((int)y0f + 1, 0), PH - 1);
        const float* __restrict__ b = g_sp + n * (PH * PW);
        if (t < PW)            r0s[t] = b[y0 * PW + t];
        else if (t < 2 * PW)   r1s[t - PW] = b[y1 * PW + (t - PW)];
    }
    __syncthreads();

    float sy = (r + 0.5f) * ((float)PH / OH) - 0.5f;
    float wy = sy - floorf(sy);
    float4 o;
    float* op = &o.x;
    #pragma unroll
    for (int k = 0; k < 4; k++) {
        int c = 4 * t + k;
        float sx = (c + 0.5f) * ((float)PW / OW) - 0.5f;
        float x0f = floorf(sx);
        float wx = sx - x0f;
        int x0 = min(max((int)x0f, 0), PW - 1);
        int x1 = min(max((int)x0f + 1, 0), PW - 1);
        float top = r0s[x0] + (r0s[x1] - r0s[x0]) * wx;
        float bot = r1s[x0] + (r1s[x1] - r1s[x0]) * wx;
        op[k] = top + (bot - top) * wy;
    }
    *(float4*)(out + ((size_t)n * OH + r) * OW + 4 * t) = o;
}

// ---------------------------------------------------------------------------
extern "C" void kernel_launch(void* const* d_in, const int* in_sizes, int n_in,
                              void* d_out, int out_size) {
    (void)in_sizes; (void)n_in; (void)out_size;
    const float* feats  = (const float*)d_in[0];
    const float* nfeats = (const float*)d_in[1];
    float* out = (float*)d_out;  // [0..7] = scores, [8..] = scores_pixel

    cudaFuncSetAttribute(gemm_max_k,
                         cudaFuncAttributeMaxDynamicSharedMemorySize, SMEM_DYN);

    norm_k<<<(N1 + N2) * P / 8, 256>>>(feats, nfeats);
    dim3 ggrid(P / BM, N1 * N2 * 2);  // 1024 units: (pblock, pair*2 + qhalf)
    gemm_max_k<<<ggrid, 256, SMEM_DYN>>>();
    reduce_k<<<N1, P>>>(out);
    resize_k<<<N1 * OH, 128>>>(out + N1);
}

// round 16
// speedup vs baseline: 1.0987x; 1.0058x over previous
#include <cuda_runtime.h>
#include <cuda_bf16.h>
#include <math.h>
#include <stdint.h>

// Problem constants
#define N1 8
#define N2 8
#define P  1024
#define D  768
#define PH 32
#define PW 32
#define OH 512
#define OW 512

// GEMM tiling — INT8 IMMA path (mma.sync m16n8k32.s8), q-split units.
#define BM 128
#define BN 128
#define BK 64                     // 64 int8 = 64B per tile row
#define STAGES 4                  // 4-deep ring: 2 groups of latency slack
#define KSTEPS (D / BK)           // 12
#define QSTEPS_U 4                // q-tiles per unit (half of 8)
#define NSTEP  (KSTEPS * QSTEPS_U)  // 48
#define TILE_BYTES  8192          // 128 rows * 64 B
#define STAGE_BYTES (2 * TILE_BYTES)
#define SMEM_TILES  (STAGES * STAGE_BYTES)   // 65536
#define SMEM_SBV    SMEM_TILES               // 128 floats of B scales
#define SMEM_DYN    (SMEM_TILES + 512)

#define ROWS_PER_BLK 8            // resize: output rows per block

// Scratch (no cudaMalloc allowed)
__device__ int8_t g_Fq[N1 * P * D];   // normalized feats, int8 (per-row scaled)
__device__ int8_t g_Gq[N2 * P * D];   // normalized nfeats, int8
__device__ float  g_sF[N1 * P];       // per-row scales for F
__device__ float  g_sG[N2 * P];       // per-row scales for G
__device__ float  g_spatch[N1 * N2 * P];  // biased max cos: cmax*sF + 2 (atomic)
__device__ float  g_sp[N1 * P];       // mean over m

// ---------------------------------------------------------------------------
// Helpers
// ---------------------------------------------------------------------------
__device__ __forceinline__ uint32_t cvta_s(const void* p) {
    return (uint32_t)__cvta_generic_to_shared(p);
}

#define CPA16(dst, src) \
    asm volatile("cp.async.cg.shared.global [%0], [%1], 16;\n" :: "r"(dst), "l"(src))
#define CPA_COMMIT()  asm volatile("cp.async.commit_group;\n" ::: "memory")
#define CPA_WAIT2()   asm volatile("cp.async.wait_group 2;\n" ::: "memory")

__device__ __forceinline__ void ldsm4(uint32_t& r0, uint32_t& r1, uint32_t& r2,
                                      uint32_t& r3, uint32_t a) {
    asm volatile("ldmatrix.sync.aligned.m8n8.x4.shared.b16 {%0,%1,%2,%3}, [%4];\n"
                 : "=r"(r0), "=r"(r1), "=r"(r2), "=r"(r3) : "r"(a));
}

__device__ __forceinline__ void mma16832s8(int* c, const uint32_t* a,
                                           const uint32_t* b) {
    asm volatile(
        "mma.sync.aligned.m16n8k32.row.col.s32.s8.s8.s32 "
        "{%0,%1,%2,%3}, {%4,%5,%6,%7}, {%8,%9}, {%0,%1,%2,%3};\n"
        : "+r"(c[0]), "+r"(c[1]), "+r"(c[2]), "+r"(c[3])
        : "r"(a[0]), "r"(a[1]), "r"(a[2]), "r"(a[3]), "r"(b[0]), "r"(b[1]));
}

// Tile row = 64 int8 = 64B = 4 chunks of 16B. XOR swizzle: conflict-free
// ldmatrix (8 rows at fixed logical chunk hit 8 distinct 16B slots mod 128B).
__device__ __forceinline__ uint32_t swaddr(int row, int ch) {
    return (uint32_t)((row << 6) | (((ch ^ ((row >> 1) & 3)) & 3) << 4));
}

// ---------------------------------------------------------------------------
// Kernel 1: row-normalize -> per-row-scaled int8, warp-per-row (no block
// barriers; MLP=6 per lane hides DRAM latency). Also zero-init g_spatch.
// grid = 2048 blocks x 256 threads (8 warps = 8 rows per block).
// ---------------------------------------------------------------------------
__global__ void norm_k(const float* __restrict__ feats,
                       const float* __restrict__ nfeats) {
    const int t = threadIdx.x;

    // init g_spatch: first 256 blocks zero 256 entries each (65536 total).
    // Keys are >= 0.95, so 0.0f is the identity for float-max.
    if (blockIdx.x < 256)
        g_spatch[(size_t)blockIdx.x * 256 + t] = 0.0f;

    const int row = blockIdx.x * 8 + (t >> 5);  // 0..16383
    const int lane = t & 31;

    const float* src;
    int8_t* dst;
    float* sdst;
    int srow;
    if (row < N1 * P) {
        src = feats + (size_t)row * D;
        dst = g_Fq + (size_t)row * D;
        sdst = g_sF; srow = row;
    } else {
        int r = row - N1 * P;
        src = nfeats + (size_t)r * D;
        dst = g_Gq + (size_t)r * D;
        sdst = g_sG; srow = r;
    }

    // 6 float4 per lane: indices lane + 32*i (coalesced)
    float4 x[6];
    float s = 0.f, am = 0.f;
    #pragma unroll
    for (int i = 0; i < 6; i++) {
        x[i] = *(const float4*)(src + (lane + 32 * i) * 4);
        s += x[i].x * x[i].x + x[i].y * x[i].y +
             x[i].z * x[i].z + x[i].w * x[i].w;
        am = fmaxf(am, fmaxf(fmaxf(fabsf(x[i].x), fabsf(x[i].y)),
                             fmaxf(fabsf(x[i].z), fabsf(x[i].w))));
    }
    #pragma unroll
    for (int off = 16; off; off >>= 1) {
        s  += __shfl_xor_sync(0xffffffffu, s, off);
        am  = fmaxf(am, __shfl_xor_sync(0xffffffffu, am, off));
    }
    // all lanes now hold the full-row sum and amax
    float scale = 127.0f / am;                         // raw-x quantizer
    if (lane == 0)
        sdst[srow] = am * rsqrtf(s) * (1.0f / 127.0f); // dequant scale

    #pragma unroll
    for (int i = 0; i < 6; i++) {
        int q0 = __float2int_rn(x[i].x * scale);
        int q1 = __float2int_rn(x[i].y * scale);
        int q2 = __float2int_rn(x[i].z * scale);
        int q3 = __float2int_rn(x[i].w * scale);
        uint32_t pk = (uint32_t)(q0 & 0xff) | ((uint32_t)(q1 & 0xff) << 8) |
                      ((uint32_t)(q2 & 0xff) << 16) | ((uint32_t)(q3 & 0xff) << 24);
        *(uint32_t*)(dst + (lane + 32 * i) * 4) = pk;
    }
}

// ---------------------------------------------------------------------------
// Kernel 2: int8 tensor-core batched GEMM + running (scaled) max over q.
// grid = (8 p-blocks, 128 = pair*2 + qhalf): 1024 units of 48 steps.
// 4-stage cp.async ring; byte-identical to R13/R15 (at IMMA issue ceiling).
// ---------------------------------------------------------------------------
__global__ __launch_bounds__(256, 2)
void gemm_max_k() {
    extern __shared__ __align__(1024) unsigned char smem[];
    const uint32_t sbase = cvta_s(smem);
    float* sbv = (float*)(smem + SMEM_SBV);  // B scales for current q-pass

    const int pair = blockIdx.y >> 1;
    const int qh   = blockIdx.y & 1;         // q-half: 0 -> q 0..511, 1 -> 512..1023
    const int qbase = qh * (QSTEPS_U * BN);  // 0 or 512
    const int8_t* __restrict__ Fb = g_Fq + (size_t)(pair >> 3) * P * D;
    const int8_t* __restrict__ Gb = g_Gq + (size_t)(pair & 7) * P * D;
    const float* __restrict__ sFp = g_sF + (size_t)(pair >> 3) * P;
    const float* __restrict__ sGp = g_sG + (size_t)(pair & 7) * P;
    const int p0 = blockIdx.x * BM;

    const int tid  = threadIdx.x;
    const int lane = tid & 31;
    const int wid  = tid >> 5;
    const int wrow = (wid >> 2) * 64;  // warp m offset (0 / 64)
    const int wcol = (wid & 3) * 32;   // warp n offset (0..96)

    // loader mapping: thread -> (row = tid>>2 [+64], chunk = tid&3)
    const int lrow   = tid >> 2;  // 0..63
    const int lchunk = tid & 3;
    const uint32_t dA0 = swaddr(lrow, lchunk);
    const uint32_t dA1 = swaddr(lrow + 64, lchunk);

    int acc[4][4][4];
    float cmax[4][2];
    #pragma unroll
    for (int i = 0; i < 4; i++) { cmax[i][0] = -1e30f; cmax[i][1] = -1e30f; }
    #pragma unroll
    for (int i = 0; i < 4; i++)
        #pragma unroll
        for (int j = 0; j < 4; j++)
            #pragma unroll
            for (int e = 0; e < 4; e++) acc[i][j][e] = 0;

    // -------- cp.async tile loader for flattened step s --------
    auto load_step = [&](int s) {
        int q0 = qbase + (s / KSTEPS) * BN;
        int k0 = (s % KSTEPS) * BK;
        uint32_t Ab = sbase + (s % STAGES) * STAGE_BYTES;
        uint32_t Bb = Ab + TILE_BYTES;
        int ke = k0 + lchunk * 16;  // int8 elements
        CPA16(Ab + dA0, Fb + ((size_t)(p0 + lrow) * D + ke));
        CPA16(Ab + dA1, Fb + ((size_t)(p0 + lrow + 64) * D + ke));
        CPA16(Bb + dA0, Gb + ((size_t)(q0 + lrow) * D + ke));
        CPA16(Bb + dA1, Gb + ((size_t)(q0 + lrow + 64) * D + ke));
    };

    // prologue: fill STAGES-1 = 3 stages
    #pragma unroll
    for (int s = 0; s < STAGES - 1; s++) {
        load_step(s);
        CPA_COMMIT();
    }

    // per-warp ldmatrix lane offsets
    const int mr = lane & 15;        // row-within-16 for ldsm
    const int cl = lane >> 4;        // 16B chunk select (0/1)
    const int qb = wcol + 2 * (lane & 3);  // this lane's base q col in tile

    int kc = 0;  // position within current q-pass
    for (int s = 0; s < NSTEP; s++) {
        CPA_WAIT2();   // step-s group done; groups s+1, s+2 may remain in flight
        __syncthreads();

        // q-pass start: stage B scales for the fold (ordered by later syncs)
        if (kc == 0 && tid < 128)
            sbv[tid] = sGp[qbase + (s / KSTEPS) * BN + tid];

        uint32_t Ab = sbase + (s % STAGES) * STAGE_BYTES;
        uint32_t Bb = Ab + TILE_BYTES;

        #pragma unroll
        for (int hk = 0; hk < 2; hk++) {  // two k32 groups in BK=64
            uint32_t a[4][4], b[4][2];
            #pragma unroll
            for (int i = 0; i < 4; i++)
                ldsm4(a[i][0], a[i][1], a[i][2], a[i][3],
                      Ab + swaddr(wrow + i * 16 + mr, hk * 2 + cl));
            #pragma unroll
            for (int j = 0; j < 2; j++) {
                uint32_t r0, r1, r2, r3;
                ldsm4(r0, r1, r2, r3,
                      Bb + swaddr(wcol + j * 16 + mr, hk * 2 + cl));
                b[2 * j][0] = r0;     b[2 * j][1] = r2;
                b[2 * j + 1][0] = r1; b[2 * j + 1][1] = r3;
            }
            #pragma unroll
            for (int i = 0; i < 4; i++)
                #pragma unroll
                for (int j = 0; j < 4; j++)
                    mma16832s8(acc[i][j], a[i], b[j]);
        }

        // issue next stage (stage (s+3)%4 was last read at step s-1)
        if (s + STAGES - 1 < NSTEP) load_step(s + STAGES - 1);
        CPA_COMMIT();

        if (++kc == KSTEPS) {  // end of a q-pass: scale by sb[q], fold max
            kc = 0;
            #pragma unroll
            for (int i = 0; i < 4; i++) {
                float m0 = cmax[i][0], m1 = cmax[i][1];
                #pragma unroll
                for (int j = 0; j < 4; j++) {
                    float s0 = sbv[qb + j * 8];
                    float s1 = sbv[qb + j * 8 + 1];
                    m0 = fmaxf(m0, fmaxf((float)acc[i][j][0] * s0,
                                         (float)acc[i][j][1] * s1));
                    m1 = fmaxf(m1, fmaxf((float)acc[i][j][2] * s0,
                                         (float)acc[i][j][3] * s1));
                    acc[i][j][0] = 0; acc[i][j][1] = 0;
                    acc[i][j][2] = 0; acc[i][j][3] = 0;
                }
                cmax[i][0] = m0; cmax[i][1] = m1;
            }
        }
    }

    // reduce max over quad lanes (columns live in lane&3; sb already applied)
    #pragma unroll
    for (int i = 0; i < 4; i++) {
        #pragma unroll
        for (int e = 0; e < 2; e++) {
            float v = cmax[i][e];
            v = fmaxf(v, __shfl_xor_sync(0xffffffffu, v, 1));
            v = fmaxf(v, __shfl_xor_sync(0xffffffffu, v, 2));
            cmax[i][e] = v;
        }
    }

    __syncthreads();  // tiles dead; reuse smem for cross-warp max
    float* red = (float*)smem;  // [4 warp_cols][128 rows]
    if ((lane & 3) == 0) {
        int base = (wid & 3) * 128 + wrow;
        int r = lane >> 2;  // 0..7
        #pragma unroll
        for (int i = 0; i < 4; i++) {
            red[base + i * 16 + r]     = cmax[i][0];
            red[base + i * 16 + r + 8] = cmax[i][1];
        }
    }
    __syncthreads();
    if (tid < 128) {
        float v = red[tid];
        v = fmaxf(v, red[128 + tid]);
        v = fmaxf(v, red[256 + tid]);
        v = fmaxf(v, red[384 + tid]);
        v = v * sFp[p0 + tid] + 2.0f;  // key in [0.95, 3.05] > 0: int-max valid
        atomicMax((int*)&g_spatch[(size_t)pair * P + p0 + tid],
                  __float_as_int(v));
    }
}

// ---------------------------------------------------------------------------
// Kernel 3: decode keys -> dist, then scores[n] = mean_m max_p,
// sp[n][p] = mean_m. dist = 0.5*sqrt(max(2 - 2*(key-2), 0)).
// ---------------------------------------------------------------------------
__global__ void reduce_k(float* __restrict__ scores) {
    const int n = blockIdx.x;
    const int p = threadIdx.x;
    float v[8];
    float s = 0.f;
    #pragma unroll
    for (int m = 0; m < 8; m++) {
        float key = g_spatch[(size_t)(n * 8 + m) * P + p];
        float c = key - 2.0f;
        v[m] = 0.5f * sqrtf(fmaxf(2.0f - 2.0f * c, 0.0f));
        s += v[m];
    }
    g_sp[n * P + p] = s * 0.125f;

    __shared__ int smax[8];
    if (p < 8) smax[p] = 0;  // dist >= 0 so int-compare == float-compare
    __syncthreads();
    #pragma unroll
    for (int m = 0; m < 8; m++) {
        float x = v[m];
        #pragma unroll
        for (int off = 16; off; off >>= 1)
            x = fmaxf(x, __shfl_xor_sync(0xffffffffu, x, off));
        if ((p & 31) == 0) atomicMax(&smax[m], __float_as_int(x));
    }
    __syncthreads();
    if (p == 0) {
        float t = 0.f;
        #pragma unroll
        for (int m = 0; m < 8; m++) t += __int_as_float(smax[m]);
        scores[n] = t * 0.125f;
    }
}

// ---------------------------------------------------------------------------
// Kernel 4: bilinear resize (8,32,32) -> (8,512,512).
// One block per 8 output rows (grid 512 x 128): the whole 32x32 sp image is
// staged in smem once; x-interp coefficients computed once per thread and
// reused across rows; each thread writes one float4 per row.
// ---------------------------------------------------------------------------
__global__ void resize_k(float* __restrict__ out) {
    const int n  = blockIdx.x / (OH / ROWS_PER_BLK);        // image
    const int r0 = (blockIdx.x % (OH / ROWS_PER_BLK)) * ROWS_PER_BLK;
    const int t  = threadIdx.x;                              // 0..127

    __shared__ float sps[PH * PW];  // full 32x32 sp image (4 KB)
    {
        const float* __restrict__ b = g_sp + n * (PH * PW);
        #pragma unroll
        for (int i = 0; i < (PH * PW) / 128; i++)
            sps[t + 128 * i] = b[t + 128 * i];
    }
    __syncthreads();

    // x coefficients for this thread's 4 pixels (columns 4t..4t+3), reused
    // across all ROWS_PER_BLK rows.
    int x0[4], x1[4];
    float wx[4];
    #pragma unroll
    for (int k = 0; k < 4; k++) {
        int c = 4 * t + k;
        float sx = (c + 0.5f) * ((float)PW / OW) - 0.5f;
        float x0f = floorf(sx);
        wx[k] = sx - x0f;
        x0[k] = min(max((int)x0f, 0), PW - 1);
        x1[k] = min(max((int)x0f + 1, 0), PW - 1);
    }

    float* __restrict__ obase = out + ((size_t)n * OH + r0) * OW + 4 * t;
    #pragma unroll
    for (int rr = 0; rr < ROWS_PER_BLK; rr++) {
        int r = r0 + rr;
        float sy = (r + 0.5f) * ((float)PH / OH) - 0.5f;
        float y0f = floorf(sy);
        float wy = sy - y0f;
        int y0 = min(max((int)y0f, 0), PH - 1);
        int y1 = min(max((int)y0f + 1, 0), PH - 1);
        const float* r0s = sps + y0 * PW;
        const float* r1s = sps + y1 * PW;

        float4 o;
        float* op = &o.x;
        #pragma unroll
        for (int k = 0; k < 4; k++) {
            float top = r0s[x0[k]] + (r0s[x1[k]] - r0s[x0[k]]) * wx[k];
            float bot = r1s[x0[k]] + (r1s[x1[k]] - r1s[x0[k]]) * wx[k];
            op[k] = top + (bot - top) * wy;
        }
        *(float4*)(obase + (size_t)rr * OW) = o;
    }
}

// ---------------------------------------------------------------------------
extern "C" void kernel_launch(void* const* d_in, const int* in_sizes, int n_in,
                              void* d_out, int out_size) {
    (void)in_sizes; (void)n_in; (void)out_size;
    const float* feats  = (const float*)d_in[0];
    const float* nfeats = (const float*)d_in[1];
    float* out = (float*)d_out;  // [0..7] = scores, [8..] = scores_pixel

    cudaFuncSetAttribute(gemm_max_k,
                         cudaFuncAttributeMaxDynamicSharedMemorySize, SMEM_DYN);

    norm_k<<<(N1 + N2) * P / 8, 256>>>(feats, nfeats);
    dim3 ggrid(P / BM, N1 * N2 * 2);  // 1024 units: (pblock, pair*2 + qhalf)
    gemm_max_k<<<ggrid, 256, SMEM_DYN>>>();
    reduce_k<<<N1, P>>>(out);
    resize_k<<<N1 * (OH / ROWS_PER_BLK), 128>>>(out + N1);
}